// round 9
// baseline (speedup 1.0000x reference)
#include <cuda_runtime.h>
#include <cuda_bf16.h>
#include <cstdint>

// CumulativeNormalizer: x [32, 512, 4000] fp32.
// out[b,f,t] = (x[t] - mean(x[0..t])) / sqrt(var(x[0..t]) + 1e-4)
//
// One 256-thread block per 4 rows; double-buffered cp.async pipeline so the
// next row's HBM load overlaps the current row's scan/epilogue/store.
// Per row: stage to shared (padded, conflict-free), thread-local 16-elem
// totals + warp scan + cross-warp combine, epilogue in place, coalesced
// streaming store. Identity: out = (x*c - S) * rsqrt(c*Q - S^2 + eps*c^2).

#define FRAMES  4000
#define ROWS    (32 * 512)
#define EPS     1e-4f
#define THREADS 256
#define SEG     16
#define ACTIVE  250                            // 250 * 16 = 4000
#define VEC4    (FRAMES / 4)                   // 1000 float4 per row
#define PADDED  (FRAMES + 4 * (FRAMES / 32))   // 4500 floats
#define RPB     4                              // rows per block
#define NBUF    2

__device__ __forceinline__ int padi(int i) { return i + ((i >> 5) << 2); }

// Issue the cp.async stage of one row into a shared buffer + commit group.
__device__ __forceinline__ void stage_row(const float* __restrict__ xr,
                                          float* buf, int tid) {
    const unsigned sbase = (unsigned)__cvta_generic_to_shared(buf);
    #pragma unroll
    for (int k = 0; k < 4; k++) {
        const int i4 = tid + THREADS * k;
        if (i4 < VEC4) {
            const int g = i4 * 4;
            const unsigned dst = sbase + (unsigned)(padi(g) * 4);
            asm volatile("cp.async.cg.shared.global [%0], [%1], 16;\n"
                         :: "r"(dst), "l"(xr + g));
        }
    }
    asm volatile("cp.async.commit_group;\n");
}

// Scan + normalize one staged row in place, then write it out (coalesced).
// Caller guarantees the buffer is loaded and a barrier has been passed.
__device__ __forceinline__ void process_row(float* sd, float* swS, float* swQ,
                                            float* __restrict__ yr,
                                            int tid, int lane, int w) {
    // ---- Per-thread segment totals over 16 contiguous frames ----
    float S = 0.f, Q = 0.f;
    if (tid < ACTIVE) {
        const int p0 = padi(tid * SEG);
        #pragma unroll
        for (int j = 0; j < 4; j++) {
            const float4 v = *reinterpret_cast<const float4*>(&sd[p0 + 4 * j]);
            S += v.x + v.y + v.z + v.w;
            Q = fmaf(v.x, v.x, Q);
            Q = fmaf(v.y, v.y, Q);
            Q = fmaf(v.z, v.z, Q);
            Q = fmaf(v.w, v.w, Q);
        }
    }

    // ---- Warp inclusive scan over segment totals ----
    const unsigned FULL = 0xFFFFFFFFu;
    float is = S, iq = Q;
    #pragma unroll
    for (int off = 1; off < 32; off <<= 1) {
        const float ts = __shfl_up_sync(FULL, is, off);
        const float tq = __shfl_up_sync(FULL, iq, off);
        if (lane >= off) { is += ts; iq += tq; }
    }
    if (lane == 31) { swS[w] = is; swQ[w] = iq; }
    __syncthreads();

    // ---- Cross-warp exclusive offset (broadcast reads) ----
    float offS = 0.f, offQ = 0.f;
    #pragma unroll
    for (int ww = 0; ww < 7; ww++) {
        if (ww < w) { offS += swS[ww]; offQ += swQ[ww]; }
    }
    const float baseS = offS + (is - S);
    const float baseQ = offQ + (iq - Q);

    // ---- Epilogue: running accumulate inside segment, normalize in place ----
    if (tid < ACTIVE) {
        const int p0 = padi(tid * SEG);
        float s = baseS, q = baseQ;
        float c = (float)(tid * SEG + 1);
        #pragma unroll
        for (int j = 0; j < 4; j++) {
            const float4 v = *reinterpret_cast<const float4*>(&sd[p0 + 4 * j]);
            float4 o;
            {   s += v.x; q = fmaf(v.x, v.x, q);
                float t = fmaf(c, q, -s * s); t = fmaf(EPS * c, c, t);
                o.x = fmaf(v.x, c, -s) * rsqrtf(t); c += 1.0f; }
            {   s += v.y; q = fmaf(v.y, v.y, q);
                float t = fmaf(c, q, -s * s); t = fmaf(EPS * c, c, t);
                o.y = fmaf(v.y, c, -s) * rsqrtf(t); c += 1.0f; }
            {   s += v.z; q = fmaf(v.z, v.z, q);
                float t = fmaf(c, q, -s * s); t = fmaf(EPS * c, c, t);
                o.z = fmaf(v.z, c, -s) * rsqrtf(t); c += 1.0f; }
            {   s += v.w; q = fmaf(v.w, v.w, q);
                float t = fmaf(c, q, -s * s); t = fmaf(EPS * c, c, t);
                o.w = fmaf(v.w, c, -s) * rsqrtf(t); c += 1.0f; }
            *reinterpret_cast<float4*>(&sd[p0 + 4 * j]) = o;
        }
    }
    __syncthreads();

    // ---- Unstage: shared -> global, coalesced streaming stores ----
    #pragma unroll
    for (int k = 0; k < 4; k++) {
        const int i4 = tid + THREADS * k;
        if (i4 < VEC4) {
            const int g = i4 * 4;
            const float4 v = *reinterpret_cast<const float4*>(&sd[padi(g)]);
            __stcs(reinterpret_cast<float4*>(yr + g), v);
        }
    }
}

__global__ __launch_bounds__(THREADS)
void cumnorm_kernel(const float* __restrict__ x, float* __restrict__ out) {
    __shared__ float sd[NBUF][PADDED];   // 2 x 18000 B
    __shared__ float swS[8];
    __shared__ float swQ[8];

    const int tid  = threadIdx.x;
    const int lane = tid & 31;
    const int w    = tid >> 5;
    const int row0 = blockIdx.x * RPB;

    // Prime the pipeline: rows 0 and 1 in flight.
    stage_row(x + (size_t)row0 * FRAMES,       sd[0], tid);
    stage_row(x + (size_t)(row0 + 1) * FRAMES, sd[1], tid);

    #pragma unroll
    for (int r = 0; r < RPB; r++) {
        // Wait until this row's group has landed (keep 1 group in flight
        // except on the last iteration).
        if (r < RPB - 1) asm volatile("cp.async.wait_group 1;\n");
        else             asm volatile("cp.async.wait_group 0;\n");
        __syncthreads();

        process_row(sd[r & 1], swS, swQ,
                    out + (size_t)(row0 + r) * FRAMES, tid, lane, w);

        // Buffer r&1 is fully consumed after all threads pass this barrier;
        // refill it with row r+2.
        if (r + 2 < RPB) {
            __syncthreads();
            stage_row(x + (size_t)(row0 + r + 2) * FRAMES, sd[r & 1], tid);
        }
    }
}

extern "C" void kernel_launch(void* const* d_in, const int* in_sizes, int n_in,
                              void* d_out, int out_size) {
    const float* x = (const float*)d_in[0];
    float* out = (float*)d_out;
    (void)in_sizes; (void)n_in; (void)out_size;

    cumnorm_kernel<<<ROWS / RPB, THREADS>>>(x, out);   // 4096 blocks
}